// round 12
// baseline (speedup 1.0000x reference)
#include <cuda_runtime.h>

#define Bv 128
#define Tv 1024
#define Nv 64
#define U 8
#define TPB 128

// Scratch (no cudaMalloc allowed). g_ctr wraps back to 0 every full run -> graph-safe.
__device__ float g_loss[Bv];
__device__ unsigned g_ctr = 0;

#define FMA_X2(d, a, b, c) \
  asm("fma.rn.f32x2 %0, %1, %2, %3;" : "=l"(d) : "l"(a), "l"(b), "l"(c))
#define ADD_X2(d, a, b) \
  asm("add.rn.f32x2 %0, %1, %2;" : "=l"(d) : "l"(a), "l"(b))

__global__ __launch_bounds__(TPB) void crf_kernel(
    const float* __restrict__ pot, const int* __restrict__ tags,
    const int* __restrict__ seqlen, const float* __restrict__ K,
    const float* __restrict__ w, float* __restrict__ out) {
  const int b = blockIdx.x;
  const int j = threadIdx.x;           // 0..127
  const int sj = j >> 1;               // state 0..63 (thread pair per state)
  const int h = j & 1;                 // half of the i-range
  const int wid = j >> 5, lane = j & 31;
  const int L = seqlen[b];

  __shared__ float Ksh[Nv * 65];                 // padded
  __shared__ __align__(16) float fbuf[2][Nv];    // ping-pong scaled forward vector f
  __shared__ float sbase;                        // C0 broadcast
  __shared__ float redx[4], redm2[4];
  __shared__ int slast;

  const float* potb = pot + (long)b * Tv * Nv;
  const int* tagb = tags + b * Tv;

  for (int idx = j; idx < Nv * Nv; idx += TPB) {
    int row = idx >> 6, col = idx & 63;
    Ksh[row * 65 + col] = K[idx];
  }
  __syncthreads();

  // ---- sequence score: batched loads for MLP (t = j + 128u <= 1023 in-bounds) ----
  int tg[8], tp[8];
#pragma unroll
  for (int u = 0; u < 8; u++) {
    int t = j + TPB * u;
    tg[u] = tagb[t];
    tp[u] = tagb[t > 0 ? t - 1 : 0];
  }
  float pv[8];
#pragma unroll
  for (int u = 0; u < 8; u++) pv[u] = potb[(j + TPB * u) * Nv + tg[u]];
  float sc = 0.f;
#pragma unroll
  for (int u = 0; u < 8; u++) {
    int t = j + TPB * u;
    if (t < L) {
      sc += pv[u];
      if (t >= 1) sc += Ksh[tp[u] * 65 + tg[u]];
    }
  }
#pragma unroll
  for (int o = 16; o > 0; o >>= 1) sc += __shfl_xor_sync(0xffffffffu, sc, o);
  if (lane == 0) redx[wid] = sc;

  // ---- exp(K) for column sj, i-range [32h, 32h+32), packed f32x2 ----
  unsigned long long eK2[16];
#pragma unroll
  for (int p = 0; p < 16; p++) {
    int row = 32 * h + 2 * p;
    float e0 = __expf(Ksh[row * 65 + sj]);
    float e1 = __expf(Ksh[(row + 1) * 65 + sj]);
    asm("mov.b64 %0, {%1, %2};" : "=l"(eK2[p]) : "f"(e0), "f"(e1));
  }

  // ---- init t = 0: f0 = exp(pot0 - C0), C0 = pot[0][0] (=> f_{0,0} = 1) ----
  float a0 = potb[sj];
  if (j == 0) sbase = a0;
  float pc[U], pn[U];
#pragma unroll
  for (int u = 0; u < U; u++) {          // pot rows for t = 1..U (clamped)
    int t = 1 + u; if (t > L - 1) t = L - 1;
    pc[u] = potb[t * Nv + sj];
  }
  __syncthreads();
  float sscore = (redx[0] + redx[1]) + (redx[2] + redx[3]);
  float C0 = sbase;
  float fj = __expf(a0 - C0);            // thread-pair-local last f value
  if (h == 0) fbuf[1][sj] = fj;
  float acc = C0 * 1.4426950408889634f;  // running -log2(c_t); every thread keeps it
  __syncthreads();

  // ---- main scan. Pair-split dot: 16 packed FMAs/thread + shfl_xor(1) combine.
  //      Chain: BAR -> LDS -> 16xFMA issue -> combine -> shfl -> mul -> STS. ----
  for (int tb = 1; tb < L; tb += U) {
    const int nb = tb + U;
#pragma unroll
    for (int u = 0; u < U; u++) {        // prefetch next chunk (clamped, branch-free)
      int t = nb + u; if (t > L - 1) t = L - 1;
      pn[u] = potb[t * Nv + sj];
    }
    float ec[U];                          // p_t = exp(pot) for this chunk (off-chain)
#pragma unroll
    for (int u = 0; u < U; u++) ec[u] = __expf(pc[u]);
#pragma unroll
    for (int u = 0; u < U; u++) {
      const int tt = tb + u;
      if (tt >= L) break;                // uniform across block
      const int rb = tt & 1, wb = rb ^ 1;
      // my 32-float half: 32h floats = 8 ulonglong2 (16B each)  [R10 bug: was 4*h]
      const ulonglong2* e2 = (const ulonglong2*)fbuf[rb] + 8 * h;

      // shadow ops (depend only on first loaded element; every thread redundant)
      float f0 = fbuf[rb][0];            // f_{t-1,0}
      float r;
      asm("rcp.approx.f32 %0, %1;" : "=f"(r) : "f"(f0));
      float pr = ec[u] * r;
      acc += __log2f(f0);

      unsigned long long a4[4] = {0ull, 0ull, 0ull, 0ull};
#pragma unroll
      for (int q = 0; q < 8; q++) {      // 16 packed FMAs = 32 scalar MACs
        ulonglong2 v = e2[q];
        FMA_X2(a4[(2 * q) & 3], v.x, eK2[2 * q], a4[(2 * q) & 3]);
        FMA_X2(a4[(2 * q + 1) & 3], v.y, eK2[2 * q + 1], a4[(2 * q + 1) & 3]);
      }
      unsigned long long t01, t23, sA;
      ADD_X2(t01, a4[0], a4[1]);
      ADD_X2(t23, a4[2], a4[3]);
      ADD_X2(sA, t01, t23);
      float slo, shi;
      asm("mov.b64 {%0, %1}, %2;" : "=f"(slo), "=f"(shi) : "l"(sA));
      float part = slo + shi;            // my half of s_{sj}
      float s = part + __shfl_xor_sync(0xffffffffu, part, 1);

      fj = s * pr;                       // f_t,sj = exp(alpha_t,sj - alpha_{t-1,0})
      if (h == 0) fbuf[wb][sj] = fj;
      __syncthreads();
    }
#pragma unroll
    for (int u = 0; u < U; u++) pc[u] = pn[u];
  }

  // ---- finish: logZ = ln2 * (acc + log2(sum_j f_{L-1,j})) ----
  float se = (h == 0) ? fj : 0.f;
#pragma unroll
  for (int o = 16; o > 0; o >>= 1) se += __shfl_xor_sync(0xffffffffu, se, o);
  if (lane == 0) redm2[wid] = se;
  __syncthreads();

  if (j == 0) {
    float sumf = (redm2[0] + redm2[1]) + (redm2[2] + redm2[3]);
    float logZ = 0.6931471805599453f * (acc + __log2f(sumf));
    g_loss[b] = -(sscore - logZ) * w[b];
    __threadfence();
    unsigned old = atomicInc(&g_ctr, Bv - 1);  // wraps to 0 each full run
    slast = (old == (unsigned)(Bv - 1)) ? 1 : 0;
  }
  __syncthreads();
  if (slast) {
    float v = __ldcg(&g_loss[j]);        // TPB == Bv: one element per thread
#pragma unroll
    for (int o = 16; o > 0; o >>= 1) v += __shfl_xor_sync(0xffffffffu, v, o);
    if (lane == 0) redx[wid] = v;
    __syncthreads();
    if (j == 0)
      out[0] = ((redx[0] + redx[1]) + (redx[2] + redx[3])) * (1.0f / (float)Bv);
  }
}

extern "C" void kernel_launch(void* const* d_in, const int* in_sizes, int n_in,
                              void* d_out, int out_size) {
  const float* pot    = (const float*)d_in[0];  // [128,1024,64] f32
  const int*   tags   = (const int*)  d_in[1];  // [128,1024] i32
  const int*   seqlen = (const int*)  d_in[2];  // [128] i32
  const float* K      = (const float*)d_in[3];  // [64,64] f32
  const float* w      = (const float*)d_in[4];  // [128] f32
  crf_kernel<<<Bv, TPB>>>(pot, tags, seqlen, K, w, (float*)d_out);
}

// round 13
// speedup vs baseline: 1.2363x; 1.2363x over previous
#include <cuda_runtime.h>

#define Bv 128
#define Tv 1024
#define Nv 64
#define U 8

// Scratch (no cudaMalloc allowed). g_ctr wraps back to 0 every full run -> graph-safe.
__device__ float g_loss[Bv];
__device__ unsigned g_ctr = 0;

#define FMA_X2(d, a, b, c) \
  asm("fma.rn.f32x2 %0, %1, %2, %3;" : "=l"(d) : "l"(a), "l"(b), "l"(c))
#define ADD_X2(d, a, b) \
  asm("add.rn.f32x2 %0, %1, %2;" : "=l"(d) : "l"(a), "l"(b))

__global__ __launch_bounds__(64) void crf_kernel(
    const float* __restrict__ pot, const int* __restrict__ tags,
    const int* __restrict__ seqlen, const float* __restrict__ K,
    const float* __restrict__ w, float* __restrict__ out) {
  const int b = blockIdx.x;
  const int j = threadIdx.x;           // state 0..63
  const int wid = j >> 5, lane = j & 31;
  const int L = seqlen[b];

  __shared__ float Ksh[Nv * 65];                 // padded for column reads
  __shared__ __align__(16) float fbuf[2][Nv];    // ping-pong scaled forward vector f
  __shared__ float sbase;                        // C0 broadcast
  __shared__ float redx[2], redm2[2];
  __shared__ int slast;

  const float* potb = pot + (long)b * Tv * Nv;
  const int* tagb = tags + b * Tv;

  for (int i = 0; i < Nv; i++) Ksh[i * 65 + j] = K[i * Nv + j];
  __syncthreads();

  // ---- sequence score: batched loads for MLP (t = j + 64u <= 1023 in-bounds) ----
  int tg[16], tp[16];
#pragma unroll
  for (int u = 0; u < 16; u++) {
    int t = j + 64 * u;
    tg[u] = tagb[t];
    tp[u] = tagb[t > 0 ? t - 1 : 0];
  }
  float pv[16];
#pragma unroll
  for (int u = 0; u < 16; u++) pv[u] = potb[(j + 64 * u) * Nv + tg[u]];
  float sc = 0.f;
#pragma unroll
  for (int u = 0; u < 16; u++) {
    int t = j + 64 * u;
    if (t < L) {
      sc += pv[u];
      if (t >= 1) sc += Ksh[tp[u] * 65 + tg[u]];
    }
  }
#pragma unroll
  for (int o = 16; o > 0; o >>= 1) sc += __shfl_xor_sync(0xffffffffu, sc, o);
  if (lane == 0) redx[wid] = sc;

  // ---- exp(K) column j, packed f32x2 pairs along i ----
  unsigned long long eK2[32];
#pragma unroll
  for (int p = 0; p < 32; p++) {
    float e0 = __expf(Ksh[(2 * p) * 65 + j]);
    float e1 = __expf(Ksh[(2 * p + 1) * 65 + j]);
    asm("mov.b64 %0, {%1, %2};" : "=l"(eK2[p]) : "f"(e0), "f"(e1));
  }

  // ---- init t = 0: f0 = exp(pot0 - C0), C0 = pot[0][0] (=> f_{0,0} = 1) ----
  float a0 = potb[j];
  if (j == 0) sbase = a0;
  float pc[U], pn[U];
#pragma unroll
  for (int u = 0; u < U; u++) {          // pot rows for t = 1..U (clamped)
    int t = 1 + u; if (t > L - 1) t = L - 1;
    pc[u] = potb[t * Nv + j];
  }
  __syncthreads();
  float sscore = redx[0] + redx[1];
  float C0 = sbase;
  float fj = __expf(a0 - C0);            // thread-local last f value
  fbuf[1][j] = fj;
  float acc = C0 * 1.4426950408889634f;  // running -log2(c_t); exact from here on
  __syncthreads();

  // ---- main scan. Chain: BAR -> LDS -> 32 packed FMA -> tree -> mul -> STS.
  //      Normalizer is a POWER OF TWO from f_{t-1,0}'s exponent bits: pure ALU,
  //      exact bookkeeping (acc += k), no MUFU in the loop body. ----
  for (int tb = 1; tb < L; tb += U) {
    const int nb = tb + U;
#pragma unroll
    for (int u = 0; u < U; u++) {        // prefetch next chunk (clamped, branch-free)
      int t = nb + u; if (t > L - 1) t = L - 1;
      pn[u] = potb[t * Nv + j];
    }
    float ec[U];                          // p_t = exp(pot) for this chunk (off-chain)
#pragma unroll
    for (int u = 0; u < U; u++) ec[u] = __expf(pc[u]);
#pragma unroll
    for (int u = 0; u < U; u++) {
      const int tt = tb + u;
      if (tt >= L) break;                // uniform across block
      const int rb = tt & 1, wb = rb ^ 1;
      const ulonglong2* e2 = (const ulonglong2*)fbuf[rb];

      // first vector load; f_{t-1,0} is its low float (no extra LDS)
      ulonglong2 v0 = e2[0];
      float f0, f1d;
      asm("mov.b64 {%0, %1}, %2;" : "=f"(f0), "=f"(f1d) : "l"(v0.x));
      unsigned eb = __float_as_uint(f0) & 0x7F800000u;
      float r = __uint_as_float(0x7F000000u - eb);       // 2^-(E-127), exact
      acc += (float)(int)(eb >> 23) - 127.0f;            // k, exact
      float pr = ec[u] * r;

      unsigned long long a4[4] = {0ull, 0ull, 0ull, 0ull};
      FMA_X2(a4[0], v0.x, eK2[0], a4[0]);
      FMA_X2(a4[1], v0.y, eK2[1], a4[1]);
#pragma unroll
      for (int q = 1; q < 16; q++) {     // remaining 30 packed FMAs, 4 chains
        ulonglong2 v = e2[q];
        FMA_X2(a4[(2 * q) & 3], v.x, eK2[2 * q], a4[(2 * q) & 3]);
        FMA_X2(a4[(2 * q + 1) & 3], v.y, eK2[2 * q + 1], a4[(2 * q + 1) & 3]);
      }
      unsigned long long t01, t23, sA;
      ADD_X2(t01, a4[0], a4[1]);
      ADD_X2(t23, a4[2], a4[3]);
      ADD_X2(sA, t01, t23);
      float slo, shi;
      asm("mov.b64 {%0, %1}, %2;" : "=f"(slo), "=f"(shi) : "l"(sA));
      float s = slo + shi;

      fj = s * pr;                       // f_t,j
      fbuf[wb][j] = fj;
      __syncthreads();
    }
#pragma unroll
    for (int u = 0; u < U; u++) pc[u] = pn[u];
  }

  // ---- finish: logZ = ln2 * (acc + log2(sum_j f_{L-1,j})) ----
  float se = fj;
#pragma unroll
  for (int o = 16; o > 0; o >>= 1) se += __shfl_xor_sync(0xffffffffu, se, o);
  if (lane == 0) redm2[wid] = se;
  __syncthreads();

  if (j == 0) {
    float sumf = redm2[0] + redm2[1];
    float logZ = 0.6931471805599453f * (acc + __log2f(sumf));
    g_loss[b] = -(sscore - logZ) * w[b];
    __threadfence();
    unsigned old = atomicInc(&g_ctr, Bv - 1);  // wraps to 0 each full run
    slast = (old == (unsigned)(Bv - 1)) ? 1 : 0;
  }
  __syncthreads();
  if (slast) {
    float v = __ldcg(&g_loss[j]) + __ldcg(&g_loss[j + 64]);
#pragma unroll
    for (int o = 16; o > 0; o >>= 1) v += __shfl_xor_sync(0xffffffffu, v, o);
    if (lane == 0) redx[wid] = v;
    __syncthreads();
    if (j == 0) out[0] = (redx[0] + redx[1]) * (1.0f / (float)Bv);
  }
}

extern "C" void kernel_launch(void* const* d_in, const int* in_sizes, int n_in,
                              void* d_out, int out_size) {
  const float* pot    = (const float*)d_in[0];  // [128,1024,64] f32
  const int*   tags   = (const int*)  d_in[1];  // [128,1024] i32
  const int*   seqlen = (const int*)  d_in[2];  // [128] i32
  const float* K      = (const float*)d_in[3];  // [64,64] f32
  const float* w      = (const float*)d_in[4];  // [128] f32
  crf_kernel<<<Bv, Nv>>>(pot, tags, seqlen, K, w, (float*)d_out);
}